// round 7
// baseline (speedup 1.0000x reference)
#include <cuda_runtime.h>
#include <math.h>

// Problem shape (fixed by the dataset)
#define BB   2048   // batch rows
#define MM   8192   // memory rows
#define DD   1024   // feature dim
#define HH   2048   // hidden dim (2d)
#define OO   1000   // output dim

// ---------------- scratch (static device globals; no allocs allowed) -------
__device__ float g_xn[(size_t)BB * DD];       // normalized encoder_output
__device__ float g_yn[(size_t)MM * DD];       // normalized memory_set
__device__ float g_z [(size_t)BB * MM];       // similarity scores
__device__ int   g_nnz[BB];                   // per-row support size
__device__ int   g_idx[(size_t)BB * MM];      // compacted support indices
__device__ float g_w  [(size_t)BB * MM];      // compacted weights
__device__ float g_mv [(size_t)BB * DD];      // memory vector
__device__ float g_h  [(size_t)BB * HH];      // hidden activations

// ---------------- packed fp32x2 FMA (Blackwell FFMA2, PTX-only) ------------
__device__ __forceinline__ float2 ffma2(float2 a, float2 b, float2 c) {
    asm("fma.rn.f32x2 %0, %1, %2, %0;"
        : "+l"(*reinterpret_cast<unsigned long long*>(&c))
        : "l"(*reinterpret_cast<unsigned long long*>(&a)),
          "l"(*reinterpret_cast<unsigned long long*>(&b)));
    return c;
}

// ---------------- block reductions (256 threads) ----------------------------
__device__ __forceinline__ float block_sum256(float v, float* sm) {
    #pragma unroll
    for (int o = 16; o; o >>= 1) v += __shfl_xor_sync(0xffffffffu, v, o);
    __syncthreads();                       // protect smem reuse across calls
    if ((threadIdx.x & 31) == 0) sm[threadIdx.x >> 5] = v;
    __syncthreads();
    float s = 0.f;
    #pragma unroll
    for (int w = 0; w < 8; w++) s += sm[w];
    return s;
}

__device__ __forceinline__ float block_max256(float v, float* sm) {
    #pragma unroll
    for (int o = 16; o; o >>= 1) v = fmaxf(v, __shfl_xor_sync(0xffffffffu, v, o));
    __syncthreads();
    if ((threadIdx.x & 31) == 0) sm[threadIdx.x >> 5] = v;
    __syncthreads();
    float s = -1e30f;
    #pragma unroll
    for (int w = 0; w < 8; w++) s = fmaxf(s, sm[w]);
    return s;
}

// ---------------- kernel 1: row normalization -------------------------------
// one CTA (256 threads) per row; D = 1024 -> exactly one float4 per thread
__global__ __launch_bounds__(256) void normalize_kernel(
        const float* __restrict__ in, float* __restrict__ out) {
    __shared__ float sm[8];
    int row = blockIdx.x;
    const float4* ip = reinterpret_cast<const float4*>(in + (size_t)row * DD);
    float4 v = ip[threadIdx.x];
    float s = v.x*v.x + v.y*v.y + v.z*v.z + v.w*v.w;
    s = block_sum256(s, sm);
    float inv = 1.0f / sqrtf(s + 1e-6f);
    v.x *= inv; v.y *= inv; v.z *= inv; v.w *= inv;
    reinterpret_cast<float4*>(out + (size_t)row * DD)[threadIdx.x] = v;
}

// ---------------- kernel 2: tiled fp32 GEMM (FFMA2 microkernel) --------------
// C[M,N] = A[M,K] * op(B)   (+bias) (+relu)
//   TRANSB = true : B is [N,K] row-major (C = A * B^T)
//   TRANSB = false: B is [K,N] row-major
// BM=BN=128, BK=16, 256 threads, 8x8 per thread (as 8x4 float2 accumulators).
// M % 128 == 0 and K % 16 == 0 are assumed (true for all call sites);
// N is bounds-checked (needed for N=1000).
template<bool TRANSB, bool RELU, bool BIAS>
__global__ __launch_bounds__(256) void gemm128(
        const float* __restrict__ A, const float* __restrict__ B,
        const float* __restrict__ bias, float* __restrict__ C,
        int M, int N, int K) {
    __shared__ float As[16][132];
    __shared__ float Bs[16][132];

    const int tid = threadIdx.x;
    const int tx = tid & 15;          // 0..15 -> N direction
    const int ty = tid >> 4;          // 0..15 -> M direction
    const int mBase = blockIdx.y * 128;
    const int nBase = blockIdx.x * 128;

    float2 acc[8][4];
    #pragma unroll
    for (int i = 0; i < 8; i++)
        #pragma unroll
        for (int j = 0; j < 4; j++) acc[i][j] = make_float2(0.f, 0.f);

    for (int k0 = 0; k0 < K; k0 += 16) {
        // --- load A tile [128 x 16], transpose into As[k][m] ---
        #pragma unroll
        for (int i = 0; i < 2; i++) {
            int slot = tid + i * 256;          // 0..511 float4 slots
            int r  = slot >> 2;                // row in tile 0..127
            int kk = (slot & 3) * 4;           // k offset 0,4,8,12
            float4 a4 = *reinterpret_cast<const float4*>(
                A + (size_t)(mBase + r) * K + k0 + kk);
            As[kk + 0][r] = a4.x; As[kk + 1][r] = a4.y;
            As[kk + 2][r] = a4.z; As[kk + 3][r] = a4.w;
        }
        // --- load B tile into Bs[k][n] ---
        if (TRANSB) {
            #pragma unroll
            for (int i = 0; i < 2; i++) {
                int slot = tid + i * 256;
                int r  = slot >> 2;            // n in tile 0..127
                int kk = (slot & 3) * 4;
                float4 b4 = *reinterpret_cast<const float4*>(
                    B + (size_t)(nBase + r) * K + k0 + kk);
                Bs[kk + 0][r] = b4.x; Bs[kk + 1][r] = b4.y;
                Bs[kk + 2][r] = b4.z; Bs[kk + 3][r] = b4.w;
            }
        } else {
            #pragma unroll
            for (int i = 0; i < 2; i++) {
                int slot = tid + i * 256;
                int r = slot >> 5;             // k row 0..15
                int c = (slot & 31) * 4;       // n offset 0..124
                int gc = nBase + c;
                float4 b4;
                if (gc + 3 < N) {
                    b4 = *reinterpret_cast<const float4*>(
                        B + (size_t)(k0 + r) * N + gc);
                } else {
                    b4.x = (gc + 0 < N) ? B[(size_t)(k0 + r) * N + gc + 0] : 0.f;
                    b4.y = (gc + 1 < N) ? B[(size_t)(k0 + r) * N + gc + 1] : 0.f;
                    b4.z = (gc + 2 < N) ? B[(size_t)(k0 + r) * N + gc + 2] : 0.f;
                    b4.w = (gc + 3 < N) ? B[(size_t)(k0 + r) * N + gc + 3] : 0.f;
                }
                *reinterpret_cast<float4*>(&Bs[r][c]) = b4;
            }
        }
        __syncthreads();

        #pragma unroll
        for (int k = 0; k < 16; k++) {
            float4 a0 = *reinterpret_cast<const float4*>(&As[k][ty * 8]);
            float4 a1 = *reinterpret_cast<const float4*>(&As[k][ty * 8 + 4]);
            float4 b0 = *reinterpret_cast<const float4*>(&Bs[k][tx * 8]);
            float4 b1 = *reinterpret_cast<const float4*>(&Bs[k][tx * 8 + 4]);
            float  av[8] = {a0.x, a0.y, a0.z, a0.w, a1.x, a1.y, a1.z, a1.w};
            float2 bv[4] = {{b0.x, b0.y}, {b0.z, b0.w}, {b1.x, b1.y}, {b1.z, b1.w}};
            #pragma unroll
            for (int i = 0; i < 8; i++) {
                float2 aa = make_float2(av[i], av[i]);
                #pragma unroll
                for (int j = 0; j < 4; j++)
                    acc[i][j] = ffma2(aa, bv[j], acc[i][j]);
            }
        }
        __syncthreads();
    }

    // --- epilogue ---
    #pragma unroll
    for (int i = 0; i < 8; i++) {
        int row = mBase + ty * 8 + i;
        #pragma unroll
        for (int j = 0; j < 4; j++) {
            int col = nBase + tx * 8 + j * 2;
            float2 v = acc[i][j];
            if (BIAS) {
                if (col + 0 < N) v.x += __ldg(bias + col + 0);
                if (col + 1 < N) v.y += __ldg(bias + col + 1);
            }
            if (RELU) { v.x = fmaxf(v.x, 0.f); v.y = fmaxf(v.y, 0.f); }
            if (col + 0 < N) C[(size_t)row * N + col + 0] = v.x;
            if (col + 1 < N) C[(size_t)row * N + col + 1] = v.y;
        }
    }
}

// ---------------- kernel 3: sparsemax per row (bisection, sort-free) --------
// sparsemax is shift-invariant, so we feed raw cosine scores z = Xn*Yn^T.
// tau* is bracketed by [zmax-1, zmax]; f(tau)=sum relu(z-tau) is monotone.
// 30 bisection steps localize tau to ~1e-9, then tau is recovered exactly
// from the (now known) support set. Nonzero weights are compacted for the
// sparse gather in the next stage.
__global__ __launch_bounds__(256) void sparsemax_kernel(
        const float* __restrict__ Z, int* __restrict__ nnz,
        int* __restrict__ idxOut, float* __restrict__ wOut) {
    __shared__ float sm[8];
    __shared__ int cnt;
    const int row = blockIdx.x;
    const int tid = threadIdx.x;
    const float* z = Z + (size_t)row * MM;

    float v[32];
    #pragma unroll
    for (int j = 0; j < 32; j++) v[j] = z[j * 256 + tid];

    float mx = -1e30f;
    #pragma unroll
    for (int j = 0; j < 32; j++) mx = fmaxf(mx, v[j]);
    const float zmax = block_max256(mx, sm);

    float lo = zmax - 1.0f, hi = zmax;   // invariant: f(lo) >= 1 > f(hi)
    for (int it = 0; it < 30; it++) {
        float mid = 0.5f * (lo + hi);
        float s = 0.f;
        #pragma unroll
        for (int j = 0; j < 32; j++) s += fmaxf(v[j] - mid, 0.f);
        s = block_sum256(s, sm);
        if (s >= 1.0f) lo = mid; else hi = mid;
    }

    // exact tau from the identified support {z > lo}
    float ssum = 0.f, scnt = 0.f;
    #pragma unroll
    for (int j = 0; j < 32; j++)
        if (v[j] > lo) { ssum += v[j]; scnt += 1.f; }
    ssum = block_sum256(ssum, sm);
    scnt = block_sum256(scnt, sm);
    const float tau = (ssum - 1.0f) / scnt;

    if (tid == 0) cnt = 0;
    __syncthreads();
    #pragma unroll
    for (int j = 0; j < 32; j++) {
        float w = v[j] - tau;
        if (w > 0.f) {
            int p = atomicAdd(&cnt, 1);
            idxOut[(size_t)row * MM + p] = j * 256 + tid;
            wOut [(size_t)row * MM + p] = w;
        }
    }
    __syncthreads();
    if (tid == 0) nnz[row] = cnt;
}

// ---------------- kernel 4: sparse weighted gather (memory vector) ----------
// mv[row,:] = sum_t w[t] * memory_set[idx[t], :];  support size ~50 << 8192.
// memory_set (32 MB) is L2-resident, so this is ~L2-bandwidth bound and tiny.
__global__ __launch_bounds__(256) void gather_kernel(
        const float* __restrict__ mem, const int* __restrict__ nnz,
        const int* __restrict__ idx, const float* __restrict__ wv,
        float* __restrict__ MV) {
    const int row = blockIdx.x;
    const int tid = threadIdx.x;
    const int n = nnz[row];
    const int*   ip = idx + (size_t)row * MM;
    const float* wp = wv  + (size_t)row * MM;
    const int c0 = tid * 4;                 // 1024 cols / 256 threads

    float4 acc = make_float4(0.f, 0.f, 0.f, 0.f);
    int t = 0;
    for (; t + 4 <= n; t += 4) {
        int   j0 = ip[t+0], j1 = ip[t+1], j2 = ip[t+2], j3 = ip[t+3];
        float w0 = wp[t+0], w1 = wp[t+1], w2 = wp[t+2], w3 = wp[t+3];
        float4 y0 = *reinterpret_cast<const float4*>(mem + (size_t)j0 * DD + c0);
        float4 y1 = *reinterpret_cast<const float4*>(mem + (size_t)j1 * DD + c0);
        float4 y2 = *reinterpret_cast<const float4*>(mem + (size_t)j2 * DD + c0);
        float4 y3 = *reinterpret_cast<const float4*>(mem + (size_t)j3 * DD + c0);
        acc.x = fmaf(w0, y0.x, fmaf(w1, y1.x, fmaf(w2, y2.x, fmaf(w3, y3.x, acc.x))));
        acc.y = fmaf(w0, y0.y, fmaf(w1, y1.y, fmaf(w2, y2.y, fmaf(w3, y3.y, acc.y))));
        acc.z = fmaf(w0, y0.z, fmaf(w1, y1.z, fmaf(w2, y2.z, fmaf(w3, y3.z, acc.z))));
        acc.w = fmaf(w0, y0.w, fmaf(w1, y1.w, fmaf(w2, y2.w, fmaf(w3, y3.w, acc.w))));
    }
    for (; t < n; t++) {
        int j = ip[t]; float w = wp[t];
        float4 y = *reinterpret_cast<const float4*>(mem + (size_t)j * DD + c0);
        acc.x = fmaf(w, y.x, acc.x); acc.y = fmaf(w, y.y, acc.y);
        acc.z = fmaf(w, y.z, acc.z); acc.w = fmaf(w, y.w, acc.w);
    }
    *reinterpret_cast<float4*>(MV + (size_t)row * DD + c0) = acc;
}

// ---------------- launch --------------------------------------------------
extern "C" void kernel_launch(void* const* d_in, const int* in_sizes, int n_in,
                              void* d_out, int out_size) {
    (void)in_sizes; (void)n_in; (void)out_size;
    const float* enc = (const float*)d_in[0];   // [2048,1024]
    const float* mem = (const float*)d_in[1];   // [8192,1024]
    const float* W1  = (const float*)d_in[2];   // [1024,2048]
    const float* b1  = (const float*)d_in[3];   // [2048]
    const float* W2  = (const float*)d_in[4];   // [2048,1000]
    const float* b2  = (const float*)d_in[5];   // [1000]
    float* out = (float*)d_out;                 // [2048,1000]

    void *p_xn, *p_yn, *p_z, *p_nnz, *p_idx, *p_w, *p_mv, *p_h;
    cudaGetSymbolAddress(&p_xn,  g_xn);
    cudaGetSymbolAddress(&p_yn,  g_yn);
    cudaGetSymbolAddress(&p_z,   g_z);
    cudaGetSymbolAddress(&p_nnz, g_nnz);
    cudaGetSymbolAddress(&p_idx, g_idx);
    cudaGetSymbolAddress(&p_w,   g_w);
    cudaGetSymbolAddress(&p_mv,  g_mv);
    cudaGetSymbolAddress(&p_h,   g_h);
    float* xn = (float*)p_xn;  float* yn = (float*)p_yn;
    float* z  = (float*)p_z;   int*   nz = (int*)p_nnz;
    int*   ix = (int*)p_idx;   float* wv = (float*)p_w;
    float* mv = (float*)p_mv;  float* h  = (float*)p_h;

    // 1) normalize rows
    normalize_kernel<<<BB, 256>>>(enc, xn);
    normalize_kernel<<<MM, 256>>>(mem, yn);

    // 2) Z = Xn * Yn^T   [2048 x 8192]
    gemm128<true, false, false><<<dim3(MM / 128, BB / 128), 256>>>(
        xn, yn, nullptr, z, BB, MM, DD);

    // 3) sparsemax per row + sparse compaction
    sparsemax_kernel<<<BB, 256>>>(z, nz, ix, wv);

    // 4) memory_vector = weights @ memory_set (sparse gather)
    gather_kernel<<<BB, 256>>>(mem, nz, ix, wv, mv);

    // 5) h = relu(mv @ W1 + b1)   [2048 x 2048]
    gemm128<false, true, true><<<dim3(HH / 128, BB / 128), 256>>>(
        mv, W1, b1, h, BB, HH, DD);

    // 6) out = h @ W2 + b2        [2048 x 1000]
    gemm128<false, false, true><<<dim3((OO + 127) / 128, BB / 128), 256>>>(
        h, W2, b2, out, BB, OO, HH);
}

// round 8
// speedup vs baseline: 1.0003x; 1.0003x over previous
#include <cuda_runtime.h>
#include <math.h>

// Problem shape (fixed by the dataset)
#define BB   2048   // batch rows
#define MM   8192   // memory rows
#define DD   1024   // feature dim
#define HH   2048   // hidden dim (2d)
#define OO   1000   // output dim

// ---------------- scratch (static device globals; no allocs allowed) -------
__device__ float g_xn[(size_t)BB * DD];       // normalized encoder_output
__device__ float g_yn[(size_t)MM * DD];       // normalized memory_set
__device__ float g_z [(size_t)BB * MM];       // similarity scores
__device__ int   g_nnz[BB];                   // per-row support size
__device__ int   g_idx[(size_t)BB * MM];      // compacted support indices
__device__ float g_w  [(size_t)BB * MM];      // compacted weights
__device__ float g_mv [(size_t)BB * DD];      // memory vector
__device__ float g_h  [(size_t)BB * HH];      // hidden activations

// ---------------- packed fp32x2 FMA (Blackwell FFMA2, PTX-only) ------------
__device__ __forceinline__ float2 ffma2(float2 a, float2 b, float2 c) {
    asm("fma.rn.f32x2 %0, %1, %2, %0;"
        : "+l"(*reinterpret_cast<unsigned long long*>(&c))
        : "l"(*reinterpret_cast<unsigned long long*>(&a)),
          "l"(*reinterpret_cast<unsigned long long*>(&b)));
    return c;
}

// ---------------- block reductions (256 threads) ----------------------------
__device__ __forceinline__ float block_sum256(float v, float* sm) {
    #pragma unroll
    for (int o = 16; o; o >>= 1) v += __shfl_xor_sync(0xffffffffu, v, o);
    __syncthreads();                       // protect smem reuse across calls
    if ((threadIdx.x & 31) == 0) sm[threadIdx.x >> 5] = v;
    __syncthreads();
    float s = 0.f;
    #pragma unroll
    for (int w = 0; w < 8; w++) s += sm[w];
    return s;
}

__device__ __forceinline__ float block_max256(float v, float* sm) {
    #pragma unroll
    for (int o = 16; o; o >>= 1) v = fmaxf(v, __shfl_xor_sync(0xffffffffu, v, o));
    __syncthreads();
    if ((threadIdx.x & 31) == 0) sm[threadIdx.x >> 5] = v;
    __syncthreads();
    float s = -1e30f;
    #pragma unroll
    for (int w = 0; w < 8; w++) s = fmaxf(s, sm[w]);
    return s;
}

// ---------------- kernel 1: row normalization -------------------------------
// one CTA (256 threads) per row; D = 1024 -> exactly one float4 per thread
__global__ __launch_bounds__(256) void normalize_kernel(
        const float* __restrict__ in, float* __restrict__ out) {
    __shared__ float sm[8];
    int row = blockIdx.x;
    const float4* ip = reinterpret_cast<const float4*>(in + (size_t)row * DD);
    float4 v = ip[threadIdx.x];
    float s = v.x*v.x + v.y*v.y + v.z*v.z + v.w*v.w;
    s = block_sum256(s, sm);
    float inv = 1.0f / sqrtf(s + 1e-6f);
    v.x *= inv; v.y *= inv; v.z *= inv; v.w *= inv;
    reinterpret_cast<float4*>(out + (size_t)row * DD)[threadIdx.x] = v;
}

// ---------------- kernel 2: tiled fp32 GEMM (FFMA2 microkernel) --------------
// C[M,N] = A[M,K] * op(B)   (+bias) (+relu)
//   TRANSB = true : B is [N,K] row-major (C = A * B^T)
//   TRANSB = false: B is [K,N] row-major
// BM=BN=128, BK=16, 256 threads, 8x8 per thread (as 8x4 float2 accumulators).
// M % 128 == 0 and K % 16 == 0 are assumed (true for all call sites);
// N is bounds-checked (needed for N=1000).
template<bool TRANSB, bool RELU, bool BIAS>
__global__ __launch_bounds__(256) void gemm128(
        const float* __restrict__ A, const float* __restrict__ B,
        const float* __restrict__ bias, float* __restrict__ C,
        int M, int N, int K) {
    __shared__ float As[16][132];
    __shared__ float Bs[16][132];

    const int tid = threadIdx.x;
    const int tx = tid & 15;          // 0..15 -> N direction
    const int ty = tid >> 4;          // 0..15 -> M direction
    const int mBase = blockIdx.y * 128;
    const int nBase = blockIdx.x * 128;

    float2 acc[8][4];
    #pragma unroll
    for (int i = 0; i < 8; i++)
        #pragma unroll
        for (int j = 0; j < 4; j++) acc[i][j] = make_float2(0.f, 0.f);

    for (int k0 = 0; k0 < K; k0 += 16) {
        // --- load A tile [128 x 16], transpose into As[k][m] ---
        #pragma unroll
        for (int i = 0; i < 2; i++) {
            int slot = tid + i * 256;          // 0..511 float4 slots
            int r  = slot >> 2;                // row in tile 0..127
            int kk = (slot & 3) * 4;           // k offset 0,4,8,12
            float4 a4 = *reinterpret_cast<const float4*>(
                A + (size_t)(mBase + r) * K + k0 + kk);
            As[kk + 0][r] = a4.x; As[kk + 1][r] = a4.y;
            As[kk + 2][r] = a4.z; As[kk + 3][r] = a4.w;
        }
        // --- load B tile into Bs[k][n] ---
        if (TRANSB) {
            #pragma unroll
            for (int i = 0; i < 2; i++) {
                int slot = tid + i * 256;
                int r  = slot >> 2;            // n in tile 0..127
                int kk = (slot & 3) * 4;
                float4 b4 = *reinterpret_cast<const float4*>(
                    B + (size_t)(nBase + r) * K + k0 + kk);
                Bs[kk + 0][r] = b4.x; Bs[kk + 1][r] = b4.y;
                Bs[kk + 2][r] = b4.z; Bs[kk + 3][r] = b4.w;
            }
        } else {
            #pragma unroll
            for (int i = 0; i < 2; i++) {
                int slot = tid + i * 256;
                int r = slot >> 5;             // k row 0..15
                int c = (slot & 31) * 4;       // n offset 0..124
                int gc = nBase + c;
                float4 b4;
                if (gc + 3 < N) {
                    b4 = *reinterpret_cast<const float4*>(
                        B + (size_t)(k0 + r) * N + gc);
                } else {
                    b4.x = (gc + 0 < N) ? B[(size_t)(k0 + r) * N + gc + 0] : 0.f;
                    b4.y = (gc + 1 < N) ? B[(size_t)(k0 + r) * N + gc + 1] : 0.f;
                    b4.z = (gc + 2 < N) ? B[(size_t)(k0 + r) * N + gc + 2] : 0.f;
                    b4.w = (gc + 3 < N) ? B[(size_t)(k0 + r) * N + gc + 3] : 0.f;
                }
                *reinterpret_cast<float4*>(&Bs[r][c]) = b4;
            }
        }
        __syncthreads();

        #pragma unroll
        for (int k = 0; k < 16; k++) {
            float4 a0 = *reinterpret_cast<const float4*>(&As[k][ty * 8]);
            float4 a1 = *reinterpret_cast<const float4*>(&As[k][ty * 8 + 4]);
            float4 b0 = *reinterpret_cast<const float4*>(&Bs[k][tx * 8]);
            float4 b1 = *reinterpret_cast<const float4*>(&Bs[k][tx * 8 + 4]);
            float  av[8] = {a0.x, a0.y, a0.z, a0.w, a1.x, a1.y, a1.z, a1.w};
            float2 bv[4] = {{b0.x, b0.y}, {b0.z, b0.w}, {b1.x, b1.y}, {b1.z, b1.w}};
            #pragma unroll
            for (int i = 0; i < 8; i++) {
                float2 aa = make_float2(av[i], av[i]);
                #pragma unroll
                for (int j = 0; j < 4; j++)
                    acc[i][j] = ffma2(aa, bv[j], acc[i][j]);
            }
        }
        __syncthreads();
    }

    // --- epilogue ---
    #pragma unroll
    for (int i = 0; i < 8; i++) {
        int row = mBase + ty * 8 + i;
        #pragma unroll
        for (int j = 0; j < 4; j++) {
            int col = nBase + tx * 8 + j * 2;
            float2 v = acc[i][j];
            if (BIAS) {
                if (col + 0 < N) v.x += __ldg(bias + col + 0);
                if (col + 1 < N) v.y += __ldg(bias + col + 1);
            }
            if (RELU) { v.x = fmaxf(v.x, 0.f); v.y = fmaxf(v.y, 0.f); }
            if (col + 0 < N) C[(size_t)row * N + col + 0] = v.x;
            if (col + 1 < N) C[(size_t)row * N + col + 1] = v.y;
        }
    }
}

// ---------------- kernel 3: sparsemax per row (bisection, sort-free) --------
// sparsemax is shift-invariant, so we feed raw cosine scores z = Xn*Yn^T.
// tau* is bracketed by [zmax-1, zmax]; f(tau)=sum relu(z-tau) is monotone.
// 30 bisection steps localize tau to ~1e-9, then tau is recovered exactly
// from the (now known) support set. Nonzero weights are compacted for the
// sparse gather in the next stage.
__global__ __launch_bounds__(256) void sparsemax_kernel(
        const float* __restrict__ Z, int* __restrict__ nnz,
        int* __restrict__ idxOut, float* __restrict__ wOut) {
    __shared__ float sm[8];
    __shared__ int cnt;
    const int row = blockIdx.x;
    const int tid = threadIdx.x;
    const float* z = Z + (size_t)row * MM;

    float v[32];
    #pragma unroll
    for (int j = 0; j < 32; j++) v[j] = z[j * 256 + tid];

    float mx = -1e30f;
    #pragma unroll
    for (int j = 0; j < 32; j++) mx = fmaxf(mx, v[j]);
    const float zmax = block_max256(mx, sm);

    float lo = zmax - 1.0f, hi = zmax;   // invariant: f(lo) >= 1 > f(hi)
    for (int it = 0; it < 30; it++) {
        float mid = 0.5f * (lo + hi);
        float s = 0.f;
        #pragma unroll
        for (int j = 0; j < 32; j++) s += fmaxf(v[j] - mid, 0.f);
        s = block_sum256(s, sm);
        if (s >= 1.0f) lo = mid; else hi = mid;
    }

    // exact tau from the identified support {z > lo}
    float ssum = 0.f, scnt = 0.f;
    #pragma unroll
    for (int j = 0; j < 32; j++)
        if (v[j] > lo) { ssum += v[j]; scnt += 1.f; }
    ssum = block_sum256(ssum, sm);
    scnt = block_sum256(scnt, sm);
    const float tau = (ssum - 1.0f) / scnt;

    if (tid == 0) cnt = 0;
    __syncthreads();
    #pragma unroll
    for (int j = 0; j < 32; j++) {
        float w = v[j] - tau;
        if (w > 0.f) {
            int p = atomicAdd(&cnt, 1);
            idxOut[(size_t)row * MM + p] = j * 256 + tid;
            wOut [(size_t)row * MM + p] = w;
        }
    }
    __syncthreads();
    if (tid == 0) nnz[row] = cnt;
}

// ---------------- kernel 4: sparse weighted gather (memory vector) ----------
// mv[row,:] = sum_t w[t] * memory_set[idx[t], :];  support size ~50 << 8192.
// memory_set (32 MB) is L2-resident, so this is ~L2-bandwidth bound and tiny.
__global__ __launch_bounds__(256) void gather_kernel(
        const float* __restrict__ mem, const int* __restrict__ nnz,
        const int* __restrict__ idx, const float* __restrict__ wv,
        float* __restrict__ MV) {
    const int row = blockIdx.x;
    const int tid = threadIdx.x;
    const int n = nnz[row];
    const int*   ip = idx + (size_t)row * MM;
    const float* wp = wv  + (size_t)row * MM;
    const int c0 = tid * 4;                 // 1024 cols / 256 threads

    float4 acc = make_float4(0.f, 0.f, 0.f, 0.f);
    int t = 0;
    for (; t + 4 <= n; t += 4) {
        int   j0 = ip[t+0], j1 = ip[t+1], j2 = ip[t+2], j3 = ip[t+3];
        float w0 = wp[t+0], w1 = wp[t+1], w2 = wp[t+2], w3 = wp[t+3];
        float4 y0 = *reinterpret_cast<const float4*>(mem + (size_t)j0 * DD + c0);
        float4 y1 = *reinterpret_cast<const float4*>(mem + (size_t)j1 * DD + c0);
        float4 y2 = *reinterpret_cast<const float4*>(mem + (size_t)j2 * DD + c0);
        float4 y3 = *reinterpret_cast<const float4*>(mem + (size_t)j3 * DD + c0);
        acc.x = fmaf(w0, y0.x, fmaf(w1, y1.x, fmaf(w2, y2.x, fmaf(w3, y3.x, acc.x))));
        acc.y = fmaf(w0, y0.y, fmaf(w1, y1.y, fmaf(w2, y2.y, fmaf(w3, y3.y, acc.y))));
        acc.z = fmaf(w0, y0.z, fmaf(w1, y1.z, fmaf(w2, y2.z, fmaf(w3, y3.z, acc.z))));
        acc.w = fmaf(w0, y0.w, fmaf(w1, y1.w, fmaf(w2, y2.w, fmaf(w3, y3.w, acc.w))));
    }
    for (; t < n; t++) {
        int j = ip[t]; float w = wp[t];
        float4 y = *reinterpret_cast<const float4*>(mem + (size_t)j * DD + c0);
        acc.x = fmaf(w, y.x, acc.x); acc.y = fmaf(w, y.y, acc.y);
        acc.z = fmaf(w, y.z, acc.z); acc.w = fmaf(w, y.w, acc.w);
    }
    *reinterpret_cast<float4*>(MV + (size_t)row * DD + c0) = acc;
}

// ---------------- launch --------------------------------------------------
extern "C" void kernel_launch(void* const* d_in, const int* in_sizes, int n_in,
                              void* d_out, int out_size) {
    (void)in_sizes; (void)n_in; (void)out_size;
    const float* enc = (const float*)d_in[0];   // [2048,1024]
    const float* mem = (const float*)d_in[1];   // [8192,1024]
    const float* W1  = (const float*)d_in[2];   // [1024,2048]
    const float* b1  = (const float*)d_in[3];   // [2048]
    const float* W2  = (const float*)d_in[4];   // [2048,1000]
    const float* b2  = (const float*)d_in[5];   // [1000]
    float* out = (float*)d_out;                 // [2048,1000]

    void *p_xn, *p_yn, *p_z, *p_nnz, *p_idx, *p_w, *p_mv, *p_h;
    cudaGetSymbolAddress(&p_xn,  g_xn);
    cudaGetSymbolAddress(&p_yn,  g_yn);
    cudaGetSymbolAddress(&p_z,   g_z);
    cudaGetSymbolAddress(&p_nnz, g_nnz);
    cudaGetSymbolAddress(&p_idx, g_idx);
    cudaGetSymbolAddress(&p_w,   g_w);
    cudaGetSymbolAddress(&p_mv,  g_mv);
    cudaGetSymbolAddress(&p_h,   g_h);
    float* xn = (float*)p_xn;  float* yn = (float*)p_yn;
    float* z  = (float*)p_z;   int*   nz = (int*)p_nnz;
    int*   ix = (int*)p_idx;   float* wv = (float*)p_w;
    float* mv = (float*)p_mv;  float* h  = (float*)p_h;

    // 1) normalize rows
    normalize_kernel<<<BB, 256>>>(enc, xn);
    normalize_kernel<<<MM, 256>>>(mem, yn);

    // 2) Z = Xn * Yn^T   [2048 x 8192]
    gemm128<true, false, false><<<dim3(MM / 128, BB / 128), 256>>>(
        xn, yn, nullptr, z, BB, MM, DD);

    // 3) sparsemax per row + sparse compaction
    sparsemax_kernel<<<BB, 256>>>(z, nz, ix, wv);

    // 4) memory_vector = weights @ memory_set (sparse gather)
    gather_kernel<<<BB, 256>>>(mem, nz, ix, wv, mv);

    // 5) h = relu(mv @ W1 + b1)   [2048 x 2048]
    gemm128<false, true, true><<<dim3(HH / 128, BB / 128), 256>>>(
        mv, W1, b1, h, BB, HH, DD);

    // 6) out = h @ W2 + b2        [2048 x 1000]
    gemm128<false, false, true><<<dim3((OO + 127) / 128, BB / 128), 256>>>(
        h, W2, b2, out, BB, OO, HH);
}